// round 5
// baseline (speedup 1.0000x reference)
#include <cuda_runtime.h>
#include <cuda_bf16.h>

// LightplaneSplatter: splat N rays x 72 samples x 16 channels into a
// (1,128,128,128,16) grid with trilinear weights, masking OOB corners.
// This version aggregates consecutive samples that fall in the same voxel
// cell (corner weights summed in registers) before emitting atomics.
//
// Inputs (metadata order):
//   d_in[0] directions  float32 [N,3]
//   d_in[1] origins     float32 [N,3]
//   d_in[2] near        float32 [N]
//   d_in[3] far         float32 [N]
//   d_in[4] encoding    float32 [N,16]
//   d_in[5] grid_idx    int32   [N]
// Output: float32 grid [1,128,128,128,16] flattened (33,554,432 elems).

#define GW 128
#define GH 128
#define GD 128
#define GC 16
#define NUM_SAMPLES 64
#define NUM_SAMPLES_INF 8
#define ST (NUM_SAMPLES + NUM_SAMPLES_INF)  // 72
#define DISPARITY_AT_INF 1e-4f

#define NSEG 3
#define SEG_LEN (ST / NSEG)  // 24

// Strides in floats
#define SXs (GC)            // 16
#define SYs (GW * GC)       // 2048
#define SZs (GH * GW * GC)  // 262144

__device__ __forceinline__ void red_add_v4(float* p, float x, float y, float z, float w) {
    asm volatile("red.global.add.v4.f32 [%0], {%1, %2, %3, %4};"
                 :: "l"(p), "f"(x), "f"(y), "f"(z), "f"(w)
                 : "memory");
}

// block: x = 4 channel-quads, y = 32 (ray,segment) groups  -> 128 threads
// grid:  x = ceil(N*NSEG / 32)
__global__ void __launch_bounds__(128) splat_kernel(
    const float* __restrict__ dirs,
    const float* __restrict__ orig,
    const float* __restrict__ nearv,
    const float* __restrict__ farv,
    const float* __restrict__ enc,
    const int*   __restrict__ gidx,
    float* __restrict__ out,
    int n_groups)
{
    const int g = blockIdx.x * blockDim.y + threadIdx.y;
    if (g >= n_groups) return;
    const int n   = g / NSEG;
    const int seg = g - n * NSEG;
    const int c4  = threadIdx.x;  // 0..3

    const float nr = nearv[n];
    const float fr = farv[n];
    const float dx_ = dirs[n * 3 + 0];
    const float dy_ = dirs[n * 3 + 1];
    const float dz_ = dirs[n * 3 + 2];
    const float ox = orig[n * 3 + 0];
    const float oy = orig[n * 3 + 1];
    const float oz = orig[n * 3 + 2];
    const int   b  = gidx[n];
    const float4 e = *reinterpret_cast<const float4*>(enc + n * GC + c4 * 4);

    const float inv_far = 1.0f / fr;

    // Aggregation state: current cell + 8 corner weight accumulators.
    int cur_bx = 0, cur_by = 0, cur_bz = 0;
    int cur_key = -1;  // -1 = no open cell
    float cw[8];
#pragma unroll
    for (int k = 0; k < 8; k++) cw[k] = 0.0f;

    const int s_begin = seg * SEG_LEN;
    const int s_end   = s_begin + SEG_LEN;

    for (int si = s_begin; si < s_end; si++) {
        float t;
        if (si < NUM_SAMPLES) {
            t = nr + (fr - nr) * (((float)si + 0.5f) * (1.0f / NUM_SAMPLES));
        } else {
            const float j = (float)(si - NUM_SAMPLES + 1) * (1.0f / NUM_SAMPLES_INF);
            const float disp = inv_far + (DISPARITY_AT_INF - inv_far) * j;
            t = 1.0f / disp;
        }

        const float vx = (ox + t * dx_ + 1.0f) * 0.5f * (float)(GW - 1);
        const float vy = (oy + t * dy_ + 1.0f) * 0.5f * (float)(GH - 1);
        const float vz = (oz + t * dz_ + 1.0f) * 0.5f * (float)(GD - 1);

        const float bxf = floorf(vx);
        const float byf = floorf(vy);
        const float bzf = floorf(vz);

        const bool maybe_in =
            (bxf >= -1.0f) && (bxf <= (float)(GW - 1)) &&
            (byf >= -1.0f) && (byf <= (float)(GH - 1)) &&
            (bzf >= -1.0f) && (bzf <= (float)(GD - 1));
        if (!maybe_in) continue;

        const int bx = (int)bxf;
        const int by = (int)byf;
        const int bz = (int)bzf;
        // bx,by,bz in [-1,127] -> +1 in [0,128] fits 9 bits
        const int key = ((bz + 1) << 18) | ((by + 1) << 9) | (bx + 1);

        if (key != cur_key) {
            // Flush previous cell.
            if (cur_key >= 0) {
                const bool x0 = (unsigned)cur_bx       < GW;
                const bool x1 = (unsigned)(cur_bx + 1) < GW;
                const bool y0 = (unsigned)cur_by       < GH;
                const bool y1 = (unsigned)(cur_by + 1) < GH;
                const bool z0 = (unsigned)cur_bz       < GD;
                const bool z1 = (unsigned)(cur_bz + 1) < GD;
                const long long basef =
                    ((((long long)b * GD + cur_bz) * GH + cur_by) * GW + cur_bx) * GC + c4 * 4;
                float* const pb = out + basef;
#pragma unroll
                for (int k = 0; k < 8; k++) {
                    const int ddx = k & 1, ddy = (k >> 1) & 1, ddz = (k >> 2) & 1;
                    const bool inb = (ddx ? x1 : x0) & (ddy ? y1 : y0) & (ddz ? z1 : z0);
                    if (inb) {
                        const float w = cw[k];
                        red_add_v4(pb + (ddz * SZs + ddy * SYs + ddx * SXs),
                                   w * e.x, w * e.y, w * e.z, w * e.w);
                    }
                }
            }
            cur_key = key;
            cur_bx = bx; cur_by = by; cur_bz = bz;
#pragma unroll
            for (int k = 0; k < 8; k++) cw[k] = 0.0f;
        }

        const float fx = vx - bxf;
        const float fy = vy - byf;
        const float fz = vz - bzf;
        const float wx0 = 1.0f - fx, wx1 = fx;
        const float wy0 = 1.0f - fy, wy1 = fy;
        const float wz0 = 1.0f - fz, wz1 = fz;
        const float w00 = wx0 * wy0, w10 = wx1 * wy0;
        const float w01 = wx0 * wy1, w11 = wx1 * wy1;
        cw[0] += w00 * wz0; cw[1] += w10 * wz0;
        cw[2] += w01 * wz0; cw[3] += w11 * wz0;
        cw[4] += w00 * wz1; cw[5] += w10 * wz1;
        cw[6] += w01 * wz1; cw[7] += w11 * wz1;
    }

    // Final flush.
    if (cur_key >= 0) {
        const bool x0 = (unsigned)cur_bx       < GW;
        const bool x1 = (unsigned)(cur_bx + 1) < GW;
        const bool y0 = (unsigned)cur_by       < GH;
        const bool y1 = (unsigned)(cur_by + 1) < GH;
        const bool z0 = (unsigned)cur_bz       < GD;
        const bool z1 = (unsigned)(cur_bz + 1) < GD;
        const long long basef =
            ((((long long)b * GD + cur_bz) * GH + cur_by) * GW + cur_bx) * GC + c4 * 4;
        float* const pb = out + basef;
#pragma unroll
        for (int k = 0; k < 8; k++) {
            const int ddx = k & 1, ddy = (k >> 1) & 1, ddz = (k >> 2) & 1;
            const bool inb = (ddx ? x1 : x0) & (ddy ? y1 : y0) & (ddz ? z1 : z0);
            if (inb) {
                const float w = cw[k];
                red_add_v4(pb + (ddz * SZs + ddy * SYs + ddx * SXs),
                           w * e.x, w * e.y, w * e.z, w * e.w);
            }
        }
    }
}

extern "C" void kernel_launch(void* const* d_in, const int* in_sizes, int n_in,
                              void* d_out, int out_size)
{
    const float* dirs  = (const float*)d_in[0];
    const float* orig  = (const float*)d_in[1];
    const float* nearv = (const float*)d_in[2];
    const float* farv  = (const float*)d_in[3];
    const float* enc   = (const float*)d_in[4];
    const int*   gidx  = (const int*)  d_in[5];
    float* out = (float*)d_out;

    const int N = in_sizes[2];  // near has one element per ray
    const int n_groups = N * NSEG;

    cudaMemsetAsync(d_out, 0, (size_t)out_size * sizeof(float));

    dim3 block(4, 32, 1);  // 4 channel-quads x 32 (ray,seg) groups = 128 threads
    dim3 grid((n_groups + 31) / 32, 1, 1);
    splat_kernel<<<grid, block>>>(dirs, orig, nearv, farv, enc, gidx, out, n_groups);
}

// round 7
// speedup vs baseline: 1.3333x; 1.3333x over previous
#include <cuda_runtime.h>
#include <cuda_bf16.h>

// LightplaneSplatter: splat N rays x 72 samples x 16 channels into a
// (1,128,128,128,16) grid with trilinear weights, masking OOB corners.
//
// R5/R6: R2 lane mapping (4 float4-lanes per sample, 8 samples per warp, one
// block per ray) + warp-synchronous segmented scan that merges consecutive
// same-cell samples so only run-tail samples issue the corner reductions.
//
// Inputs (metadata order):
//   d_in[0] directions  float32 [N,3]
//   d_in[1] origins     float32 [N,3]
//   d_in[2] near        float32 [N]
//   d_in[3] far         float32 [N]
//   d_in[4] encoding    float32 [N,16]
//   d_in[5] grid_idx    int32   [N]
// Output: float32 grid [1,128,128,128,16] flattened (33,554,432 elems).

#define GW 128
#define GH 128
#define GD 128
#define GC 16
#define NUM_SAMPLES 64
#define NUM_SAMPLES_INF 8
#define ST (NUM_SAMPLES + NUM_SAMPLES_INF)  // 72
#define DISPARITY_AT_INF 1e-4f

// Strides in floats
#define SXs (GC)            // 16
#define SYs (GW * GC)       // 2048
#define SZs (GH * GW * GC)  // 262144

__device__ __forceinline__ void red_add_v4(float* p, float x, float y, float z, float w) {
    asm volatile("red.global.add.v4.f32 [%0], {%1, %2, %3, %4};"
                 :: "l"(p), "f"(x), "f"(y), "f"(z), "f"(w)
                 : "memory");
}

// block: x = 4 channel-quads (float4 each), y = 72 samples -> 288 threads
// grid:  x = N rays
// Warp w holds samples 8w..8w+7 of one ray; lane = c4 + 4*s_local.
__global__ void __launch_bounds__(288) splat_kernel(
    const float* __restrict__ dirs,
    const float* __restrict__ orig,
    const float* __restrict__ nearv,
    const float* __restrict__ farv,
    const float* __restrict__ enc,
    const int*   __restrict__ gidx,
    float* __restrict__ out)
{
    const unsigned FULL = 0xffffffffu;
    const int n  = blockIdx.x;
    const int si = threadIdx.y;        // 0..71
    const int c4 = threadIdx.x;        // 0..3
    const int s_local = si & 7;        // sample slot within warp

    const float nr = nearv[n];
    const float fr = farv[n];

    float t;
    if (si < NUM_SAMPLES) {
        t = nr + (fr - nr) * (((float)si + 0.5f) * (1.0f / NUM_SAMPLES));
    } else {
        const float j    = (float)(si - NUM_SAMPLES + 1) * (1.0f / NUM_SAMPLES_INF);
        const float invf = 1.0f / fr;
        const float disp = invf + (DISPARITY_AT_INF - invf) * j;
        t = 1.0f / disp;
    }

    const float px = orig[n * 3 + 0] + t * dirs[n * 3 + 0];
    const float py = orig[n * 3 + 1] + t * dirs[n * 3 + 1];
    const float pz = orig[n * 3 + 2] + t * dirs[n * 3 + 2];

    const float vx = (px + 1.0f) * 0.5f * (float)(GW - 1);
    const float vy = (py + 1.0f) * 0.5f * (float)(GH - 1);
    const float vz = (pz + 1.0f) * 0.5f * (float)(GD - 1);

    const float bxf = floorf(vx);
    const float byf = floorf(vy);
    const float bzf = floorf(vz);

    // Written so NaN also fails -> OOB.
    const bool inb_sample =
        (bxf >= -1.0f) && (bxf <= (float)(GW - 1)) &&
        (byf >= -1.0f) && (byf <= (float)(GH - 1)) &&
        (bzf >= -1.0f) && (bzf <= (float)(GD - 1));

    const int bx = (int)bxf;
    const int by = (int)byf;
    const int bz = (int)bzf;

    // Cell key (-1 = OOB sample: never flushed, weights zero).
    const int key = inb_sample
        ? ((((bz + 1) << 9) | (by + 1)) << 9) | (bx + 1)
        : -1;

    // Per-sample corner weights (zero when OOB).
    float v[8];
    if (inb_sample) {
        const float fx = vx - bxf;
        const float fy = vy - byf;
        const float fz = vz - bzf;
        const float wx0 = 1.0f - fx, wx1 = fx;
        const float wy0 = 1.0f - fy, wy1 = fy;
        const float wz0 = 1.0f - fz, wz1 = fz;
        const float w00 = wx0 * wy0, w10 = wx1 * wy0;
        const float w01 = wx0 * wy1, w11 = wx1 * wy1;
        v[0] = w00 * wz0; v[1] = w10 * wz0;
        v[2] = w01 * wz0; v[3] = w11 * wz0;
        v[4] = w00 * wz1; v[5] = w10 * wz1;
        v[6] = w01 * wz1; v[7] = w11 * wz1;
    } else {
#pragma unroll
        for (int k = 0; k < 8; k++) v[k] = 0.0f;
    }

    // ---- Warp-synchronous segmented inclusive scan over samples ----
    // Segment heads: first slot, or cell differs from previous sample.
    const int prev_key = __shfl_up_sync(FULL, key, 4);
    unsigned f = (s_local == 0 || key != prev_key) ? 1u : 0u;

#pragma unroll
    for (int d = 1; d <= 4; d <<= 1) {
        float up[8];
#pragma unroll
        for (int k = 0; k < 8; k++) up[k] = __shfl_up_sync(FULL, v[k], 4 * d);
        const unsigned fup = __shfl_up_sync(FULL, f, 4 * d);
        if (s_local >= d) {
            if (!f) {
#pragma unroll
                for (int k = 0; k < 8; k++) v[k] += up[k];
            }
            f |= fup;
        }
    }

    // Run tails: last slot, or next sample is a different cell.
    const int next_key = __shfl_down_sync(FULL, key, 4);
    const bool tail = (s_local == 7) || (key != next_key);

    if (!(tail && key >= 0)) return;  // after all shuffles: safe to exit

    const int b = gidx[n];
    const float4 e = *reinterpret_cast<const float4*>(enc + n * GC + c4 * 4);

    const bool x0 = (unsigned)bx       < GW;
    const bool x1 = (unsigned)(bx + 1) < GW;
    const bool y0 = (unsigned)by       < GH;
    const bool y1 = (unsigned)(by + 1) < GH;
    const bool z0 = (unsigned)bz       < GD;
    const bool z1 = (unsigned)(bz + 1) < GD;

    const long long basef =
        ((((long long)b * GD + bz) * GH + by) * GW + bx) * GC + c4 * 4;
    float* const pb = out + basef;

#pragma unroll
    for (int k = 0; k < 8; k++) {
        const int ddx = k & 1, ddy = (k >> 1) & 1, ddz = (k >> 2) & 1;
        const bool inb = (ddx ? x1 : x0) & (ddy ? y1 : y0) & (ddz ? z1 : z0);
        if (inb) {
            const float w = v[k];
            red_add_v4(pb + (ddz * SZs + ddy * SYs + ddx * SXs),
                       w * e.x, w * e.y, w * e.z, w * e.w);
        }
    }
}

extern "C" void kernel_launch(void* const* d_in, const int* in_sizes, int n_in,
                              void* d_out, int out_size)
{
    const float* dirs  = (const float*)d_in[0];
    const float* orig  = (const float*)d_in[1];
    const float* nearv = (const float*)d_in[2];
    const float* farv  = (const float*)d_in[3];
    const float* enc   = (const float*)d_in[4];
    const int*   gidx  = (const int*)  d_in[5];
    float* out = (float*)d_out;

    const int N = in_sizes[2];  // near has one element per ray

    cudaMemsetAsync(d_out, 0, (size_t)out_size * sizeof(float));

    dim3 block(4, ST, 1);   // 4 channel-quads x 72 samples = 288 threads
    dim3 grid(N, 1, 1);
    splat_kernel<<<grid, block>>>(dirs, orig, nearv, farv, enc, gidx, out);
}